// round 6
// baseline (speedup 1.0000x reference)
#include <cuda_runtime.h>
#include <math.h>

#define NTOK   16384
#define DDIM   1024
#define HDIM   4096
#define ODIM   1024
#define NEXP   8
#define NBANDS 4
#define RR     16
#define REXT   (NBANDS*RR)      /* 64 */
#define NPAIR  (NTOK*2)         /* 32768 */

// ---------------- scratch (device globals: no allocation allowed) ----------------
__device__ float g_h[(size_t)NPAIR * HDIM];        // 512 MB intermediate activations
__device__ float g_u1ext[(size_t)NPAIR * REXT];    // SCALING*u1, band-masked
__device__ float g_u2ext[(size_t)NPAIR * REXT];    // SCALING*u2, band-masked
__device__ int   g_count[NEXP];
__device__ int   g_offset[NEXP];
__device__ int   g_cursor[NEXP];
__device__ float g_imp[NEXP];
__device__ int   g_tok[NPAIR];
__device__ float g_gw[NPAIR];
__device__ int   g_eid[NPAIR];
__device__ int   g_topi[NTOK * 2];
__device__ float g_topw[NTOK * 2];

// ---------------- helpers ----------------
__device__ __forceinline__ void ffma2(unsigned long long& d, unsigned long long a,
                                      unsigned long long b) {
    asm("fma.rn.f32x2 %0, %1, %2, %0;" : "+l"(d) : "l"(a), "l"(b));
}
__device__ __forceinline__ unsigned long long splat2(float f) {
    unsigned long long r;
    asm("mov.b64 %0, {%1, %1};" : "=l"(r) : "r"(__float_as_uint(f)));
    return r;
}
__device__ __forceinline__ float gelu_exact(float v) {
    return 0.5f * v * (1.0f + erff(v * 0.70710678118654752440f));
}

// ---------------- kernel 0: zero small accumulators ----------------
__global__ void init_kernel() {
    int t = threadIdx.x;
    if (t < NEXP) { g_count[t] = 0; g_imp[t] = 0.0f; }
}

// ---------------- kernel 1: gating (warp per token) ----------------
__global__ void gate_kernel(const float* __restrict__ x, const float* __restrict__ wg) {
    int lane = threadIdx.x & 31, warp = threadIdx.x >> 5;
    int t = blockIdx.x * 8 + warp;
    if (t >= NTOK) return;
    float acc[NEXP];
#pragma unroll
    for (int e = 0; e < NEXP; e++) acc[e] = 0.0f;
    const float* xr = x + (size_t)t * DDIM;
    for (int d = lane; d < DDIM; d += 32) {
        float xv = __ldg(xr + d);
        const float4* wr = (const float4*)(wg + (size_t)d * NEXP);
        float4 w0 = __ldg(wr), w1 = __ldg(wr + 1);
        acc[0] += xv * w0.x; acc[1] += xv * w0.y; acc[2] += xv * w0.z; acc[3] += xv * w0.w;
        acc[4] += xv * w1.x; acc[5] += xv * w1.y; acc[6] += xv * w1.z; acc[7] += xv * w1.w;
    }
#pragma unroll
    for (int off = 16; off > 0; off >>= 1) {
#pragma unroll
        for (int e = 0; e < NEXP; e++)
            acc[e] += __shfl_xor_sync(0xffffffffu, acc[e], off);
    }
    if (lane == 0) {
        float v1 = -1e30f, v2 = -1e30f; int i1 = 0, i2 = 1;
#pragma unroll
        for (int e = 0; e < NEXP; e++) {
            float v = acc[e];
            if (v > v1)      { v2 = v1; i2 = i1; v1 = v; i1 = e; }
            else if (v > v2) { v2 = v;  i2 = e; }
        }
        float ex = expf(v2 - v1);
        float inv = 1.0f / (1.0f + ex);
        float w1v = inv, w2v = ex * inv;
        g_topi[2 * t] = i1;  g_topi[2 * t + 1] = i2;
        g_topw[2 * t] = w1v; g_topw[2 * t + 1] = w2v;
        atomicAdd(&g_count[i1], 1);   atomicAdd(&g_count[i2], 1);
        atomicAdd(&g_imp[i1], w1v);   atomicAdd(&g_imp[i2], w2v);
    }
}

// ---------------- kernel 2: offsets + aux loss ----------------
__global__ void offloss_kernel(float* __restrict__ out) {
    if (threadIdx.x != 0 || blockIdx.x != 0) return;
    int off = 0;
    for (int e = 0; e < NEXP; e++) { g_offset[e] = off; g_cursor[e] = off; off += g_count[e]; }
    float mi = 0.0f, ml = 0.0f;
    for (int e = 0; e < NEXP; e++) { mi += g_imp[e]; ml += (float)g_count[e]; }
    mi *= (1.0f / NEXP); ml *= (1.0f / NEXP);
    float vi = 0.0f, vl = 0.0f;
    for (int e = 0; e < NEXP; e++) {
        float di = g_imp[e] - mi;          vi += di * di;
        float dl = (float)g_count[e] - ml; vl += dl * dl;
    }
    vi *= (1.0f / (NEXP - 1)); vl *= (1.0f / (NEXP - 1));
    out[(size_t)NTOK * ODIM] =
        0.01f * (vi / (mi * mi + 1e-10f) + vl / (ml * ml + 1e-10f));
}

// ---------------- kernel 3: scatter tokens into per-expert pair lists ----------------
__global__ void scatter_kernel() {
    int t = blockIdx.x * blockDim.x + threadIdx.x;
    if (t >= NTOK) return;
#pragma unroll
    for (int k = 0; k < 2; k++) {
        int e = g_topi[2 * t + k];
        float w = g_topw[2 * t + k];
        int p = atomicAdd(&g_cursor[e], 1);
        g_tok[p] = t; g_gw[p] = w; g_eid[p] = e;
    }
}

// ---------------- kernel 4/6: LoRA down-projection u = src @ A[e,band] ----------------
// FIRST=true:  u1 = x[tok] @ A1[e,band]  (K=DDIM)  -> g_u1ext (scaled by 2, band slot)
// FIRST=false: u2 = h[p]  @ A2[e,band]  (K=HDIM)  -> g_u2ext
template <bool FIRST>
__global__ void ured_kernel(const float* __restrict__ src, const float* __restrict__ Amat,
                            const int* __restrict__ band) {
    int lane = threadIdx.x & 31, warp = threadIdx.x >> 5;
    int p = blockIdx.x * 8 + warp;
    if (p >= NPAIR) return;
    int t = g_tok[p];
    int e = g_eid[p];
    int b = __ldg(band + t);
    const int K = FIRST ? DDIM : HDIM;
    const float* row = FIRST ? (src + (size_t)t * DDIM) : (&g_h[0] + (size_t)p * HDIM);
    const float* A = Amat + (size_t)(e * NBANDS + b) * K * RR;
    float acc[RR];
#pragma unroll
    for (int r = 0; r < RR; r++) acc[r] = 0.0f;
    for (int d = lane; d < K; d += 32) {
        float v = __ldg(row + d);
        const float4* ar = (const float4*)(A + (size_t)d * RR);
        float4 q0 = __ldg(ar + 0), q1 = __ldg(ar + 1), q2 = __ldg(ar + 2), q3 = __ldg(ar + 3);
        acc[0]  += v * q0.x; acc[1]  += v * q0.y; acc[2]  += v * q0.z; acc[3]  += v * q0.w;
        acc[4]  += v * q1.x; acc[5]  += v * q1.y; acc[6]  += v * q1.z; acc[7]  += v * q1.w;
        acc[8]  += v * q2.x; acc[9]  += v * q2.y; acc[10] += v * q2.z; acc[11] += v * q2.w;
        acc[12] += v * q3.x; acc[13] += v * q3.y; acc[14] += v * q3.z; acc[15] += v * q3.w;
    }
#pragma unroll
    for (int off = 16; off > 0; off >>= 1) {
#pragma unroll
        for (int r = 0; r < RR; r++)
            acc[r] += __shfl_xor_sync(0xffffffffu, acc[r], off);
    }
    float* ur = (FIRST ? g_u1ext : g_u2ext) + (size_t)p * REXT;
    ur[lane] = 0.0f; ur[lane + 32] = 0.0f;
    __syncwarp();
    if (lane < RR) ur[b * RR + lane] = 2.0f * acc[lane];  // SCALING folded in here
}

// ---------------- kernels 5/7: fused grouped GEMM (K augmented by 64 LoRA cols) ----
// FIRST=true : g_h[p,:] = gelu( x[tok] @ W1[e] + b1[e] + uext1 @ B1[e] )   KD=1024 N=4096
// FIRST=false: y[tok,:] += gw * ( h[p] @ W2[e] + b2[e] + uext2 @ B2[e] )   KD=4096 N=1024
template <bool FIRST, int KD, int NDIM>
__global__ void __launch_bounds__(256, 2)
gemm_kernel(const float* __restrict__ Amain,   // x (FIRST) / unused
            const float* __restrict__ Bmain,   // W1 / W2  : [E, KD, NDIM]
            const float* __restrict__ Bext,    // B1 / B2  : [E, 64, NDIM]
            const float* __restrict__ bias,    // b1 / b2  : [E, NDIM]
            float* __restrict__ Yout)          // unused / d_out y
{
    int e = blockIdx.z;
    int cnt = g_count[e];
    int rowbase = blockIdx.y * 128;
    if (rowbase >= cnt) return;
    int pstart = g_offset[e] + rowbase;
    int pend   = g_offset[e] + cnt;
    int jb     = blockIdx.x * 128;

    __shared__ float As[16][132];
    __shared__ float Bs[16][128];
    __shared__ int   srow[128];
    __shared__ float sgw[128];

    int tid = threadIdx.x;
    if (tid < 128) {
        int p = pstart + tid; if (p >= pend) p = pend - 1;
        srow[tid] = g_tok[p];
        sgw[tid]  = g_gw[p];
    }
    __syncthreads();

    int tx = tid & 15, ty = tid >> 4;
    int arow = tid >> 1;            // 0..127
    int acol = (tid & 1) * 8;       // 0 or 8
    int brow = tid >> 4;            // 0..15
    int bcol = (tid & 15) * 8;      // 0..120

    int pcl = pstart + arow; if (pcl >= pend) pcl = pend - 1;
    const float* Arow = FIRST ? (Amain + (size_t)srow[arow] * DDIM)
                              : (&g_h[0] + (size_t)pcl * HDIM);
    const float* AextRow = (FIRST ? g_u1ext : g_u2ext) + (size_t)pcl * REXT;

    unsigned long long acc[8][4] = {};

    for (int k0 = 0; k0 < KD + REXT; k0 += 16) {
        const float* as = (k0 < KD) ? (Arow + k0 + acol) : (AextRow + (k0 - KD) + acol);
        float4 av0 = __ldg((const float4*)as);
        float4 av1 = __ldg((const float4*)(as + 4));
        const float* bs = (k0 < KD)
            ? (Bmain + ((size_t)e * KD + (k0 + brow)) * NDIM + jb + bcol)
            : (Bext  + ((size_t)e * REXT + (k0 - KD + brow)) * NDIM + jb + bcol);
        float4 bv0 = __ldg((const float4*)bs);
        float4 bv1 = __ldg((const float4*)(bs + 4));

        __syncthreads();
        As[acol + 0][arow] = av0.x; As[acol + 1][arow] = av0.y;
        As[acol + 2][arow] = av0.z; As[acol + 3][arow] = av0.w;
        As[acol + 4][arow] = av1.x; As[acol + 5][arow] = av1.y;
        As[acol + 6][arow] = av1.z; As[acol + 7][arow] = av1.w;
        *(float4*)&Bs[brow][bcol]     = bv0;
        *(float4*)&Bs[brow][bcol + 4] = bv1;
        __syncthreads();

#pragma unroll
        for (int kk = 0; kk < 16; kk++) {
            float4 af0 = *(const float4*)&As[kk][ty * 4];
            float4 af1 = *(const float4*)&As[kk][64 + ty * 4];
            ulonglong2 u0 = *(const ulonglong2*)&Bs[kk][tx * 4];
            ulonglong2 u1 = *(const ulonglong2*)&Bs[kk][64 + tx * 4];
            float a[8] = {af0.x, af0.y, af0.z, af0.w, af1.x, af1.y, af1.z, af1.w};
#pragma unroll
            for (int i = 0; i < 8; i++) {
                unsigned long long s = splat2(a[i]);
                ffma2(acc[i][0], s, u0.x);
                ffma2(acc[i][1], s, u0.y);
                ffma2(acc[i][2], s, u1.x);
                ffma2(acc[i][3], s, u1.y);
            }
        }
    }

    // bias for this thread's 8 columns
    float bv[8];
#pragma unroll
    for (int j = 0; j < 4; j++) {
        bv[j]     = __ldg(bias + (size_t)e * NDIM + jb + tx * 4 + j);
        bv[4 + j] = __ldg(bias + (size_t)e * NDIM + jb + 64 + tx * 4 + j);
    }

#pragma unroll
    for (int i = 0; i < 8; i++) {
        int r = (i < 4) ? (ty * 4 + i) : (64 + ty * 4 + (i - 4));
        int p = pstart + r;
        if (p >= pend) continue;
        float v[8];
#pragma unroll
        for (int c = 0; c < 4; c++) {
            unsigned long long w = acc[i][c];
            v[c * 2]     = __uint_as_float((unsigned)w);
            v[c * 2 + 1] = __uint_as_float((unsigned)(w >> 32));
        }
        if (FIRST) {
            float hv[8];
#pragma unroll
            for (int c = 0; c < 8; c++) hv[c] = gelu_exact(v[c] + bv[c]);
            float* orow = &g_h[0] + (size_t)p * NDIM + jb;
            *(float4*)(orow + tx * 4)      = make_float4(hv[0], hv[1], hv[2], hv[3]);
            *(float4*)(orow + 64 + tx * 4) = make_float4(hv[4], hv[5], hv[6], hv[7]);
        } else {
            int tok = srow[r];
            float gw = sgw[r];
            float* yrow = Yout + (size_t)tok * NDIM + jb;
#pragma unroll
            for (int c = 0; c < 4; c++) {
                atomicAdd(yrow + tx * 4 + c,      gw * (v[c] + bv[c]));
                atomicAdd(yrow + 64 + tx * 4 + c, gw * (v[4 + c] + bv[4 + c]));
            }
        }
    }
}

// ---------------- host launcher ----------------
extern "C" void kernel_launch(void* const* d_in, const int* in_sizes, int n_in,
                              void* d_out, int out_size) {
    const float* x    = (const float*)d_in[0];
    const int*   band = (const int*)  d_in[1];
    const float* wg   = (const float*)d_in[2];
    const float* W1   = (const float*)d_in[3];
    const float* b1   = (const float*)d_in[4];
    const float* W2   = (const float*)d_in[5];
    const float* b2   = (const float*)d_in[6];
    const float* A1   = (const float*)d_in[7];
    const float* B1   = (const float*)d_in[8];
    const float* A2   = (const float*)d_in[9];
    const float* B2   = (const float*)d_in[10];
    float* out = (float*)d_out;

    // zero y (+loss slot) — d_out is poisoned before timing
    cudaMemsetAsync(d_out, 0, (size_t)out_size * sizeof(float));

    init_kernel<<<1, 32>>>();
    gate_kernel<<<NTOK / 8, 256>>>(x, wg);
    offloss_kernel<<<1, 32>>>(out);
    scatter_kernel<<<NTOK / 256, 256>>>();

    ured_kernel<true><<<NPAIR / 8, 256>>>(x, A1, band);

    gemm_kernel<true, DDIM, HDIM>
        <<<dim3(HDIM / 128, NTOK / 128, NEXP), 256>>>(x, W1, B1, b1, nullptr);

    ured_kernel<false><<<NPAIR / 8, 256>>>(nullptr, A2, band);

    gemm_kernel<false, HDIM, ODIM>
        <<<dim3(ODIM / 128, NTOK / 128, NEXP), 256>>>(nullptr, W2, B2, b2, out);

    (void)in_sizes; (void)n_in;
}

// round 8
// speedup vs baseline: 1.3242x; 1.3242x over previous
#include <cuda_runtime.h>
#include <cuda_bf16.h>
#include <math.h>
#include <stdint.h>

#define NTOK   16384
#define DDIM   1024
#define HDIM   4096
#define ODIM   1024
#define NEXP   8
#define NBANDS 4
#define RR     16
#define REXT   (NBANDS*RR)      /* 64 */
#define NPAIR  (NTOK*2)         /* 32768 */
#define NBUCK  (NEXP*NBANDS)    /* 32 */
#define MAXTILES 264            /* 32768/128 + 8 */

#define TSTRIDE 80              /* bytes per smem tile row (32 bf16 data + pad) */
#define TILEB   (128 * TSTRIDE) /* 10240 */
#define STAGEB  (4 * TILEB)     /* 40960: Ah, Al, Bh, Bl */
#define GEMM_SMEM (2 * STAGEB + 1024)

// ---------------- device-global scratch (no allocation allowed) ----------------
__device__ __nv_bfloat16 g_xh [(size_t)NPAIR * DDIM];
__device__ __nv_bfloat16 g_xl [(size_t)NPAIR * DDIM];
__device__ __nv_bfloat16 g_xeh[(size_t)NPAIR * REXT];
__device__ __nv_bfloat16 g_xel[(size_t)NPAIR * REXT];
__device__ __nv_bfloat16 g_hh [(size_t)NPAIR * HDIM];
__device__ __nv_bfloat16 g_hl [(size_t)NPAIR * HDIM];
__device__ __nv_bfloat16 g_u2h[(size_t)NPAIR * REXT];
__device__ __nv_bfloat16 g_u2l[(size_t)NPAIR * REXT];
__device__ __nv_bfloat16 g_w1h[(size_t)NEXP * HDIM * DDIM];  // [E][N=H][K=D]
__device__ __nv_bfloat16 g_w1l[(size_t)NEXP * HDIM * DDIM];
__device__ __nv_bfloat16 g_w2h[(size_t)NEXP * ODIM * HDIM];  // [E][N=O][K=H]
__device__ __nv_bfloat16 g_w2l[(size_t)NEXP * ODIM * HDIM];
__device__ __nv_bfloat16 g_b1h[(size_t)NEXP * HDIM * REXT];  // [E][N=H][K=64]
__device__ __nv_bfloat16 g_b1l[(size_t)NEXP * HDIM * REXT];
__device__ __nv_bfloat16 g_b2h[(size_t)NEXP * ODIM * REXT];
__device__ __nv_bfloat16 g_b2l[(size_t)NEXP * ODIM * REXT];

__device__ int   g_bcount[NBUCK];
__device__ int   g_bcursor[NBUCK];
__device__ int   g_count[NEXP];
__device__ int   g_offset[NEXP];
__device__ float g_imp[NEXP];
__device__ int   g_tok[NPAIR];
__device__ float g_gw[NPAIR];
__device__ int   g_eid[NPAIR];
__device__ int   g_topi[NTOK * 2];
__device__ float g_topw[NTOK * 2];
__device__ int   g_tile_e[MAXTILES];
__device__ int   g_tile_p0[MAXTILES];
__device__ int   g_ntiles;

// ---------------- small helpers ----------------
__device__ __forceinline__ float gelu_exact(float v) {
    return 0.5f * v * (1.0f + erff(v * 0.70710678118654752440f));
}
__device__ __forceinline__ uint32_t smem_u32(const void* p) {
    uint32_t a;
    asm("{ .reg .u64 t; cvta.to.shared.u64 t, %1; cvt.u32.u64 %0, t; }" : "=r"(a) : "l"(p));
    return a;
}
__device__ __forceinline__ void cp16(uint32_t dst, const void* src) {
    asm volatile("cp.async.cg.shared.global [%0], [%1], 16;" :: "r"(dst), "l"(src));
}
__device__ __forceinline__ void ldsm4(uint32_t* r, uint32_t addr) {
    asm volatile("ldmatrix.sync.aligned.m8n8.x4.shared.b16 {%0,%1,%2,%3}, [%4];"
                 : "=r"(r[0]), "=r"(r[1]), "=r"(r[2]), "=r"(r[3]) : "r"(addr));
}
__device__ __forceinline__ void mma16816(float* c, const uint32_t* a, const uint32_t* b) {
    asm volatile(
        "mma.sync.aligned.m16n8k16.row.col.f32.bf16.bf16.f32 "
        "{%0,%1,%2,%3}, {%4,%5,%6,%7}, {%8,%9}, {%0,%1,%2,%3};"
        : "+f"(c[0]), "+f"(c[1]), "+f"(c[2]), "+f"(c[3])
        : "r"(a[0]), "r"(a[1]), "r"(a[2]), "r"(a[3]), "r"(b[0]), "r"(b[1]));
}

// ---------------- kernel 0: init ----------------
__global__ void init_kernel() {
    int t = threadIdx.x;
    if (t < NBUCK) g_bcount[t] = 0;
    if (t < NEXP) g_imp[t] = 0.0f;
}

// ---------------- kernel 1: gating (warp per token) ----------------
__global__ void gate_kernel(const float* __restrict__ x, const float* __restrict__ wg,
                            const int* __restrict__ band) {
    int lane = threadIdx.x & 31, warp = threadIdx.x >> 5;
    int t = blockIdx.x * 8 + warp;
    if (t >= NTOK) return;
    float acc[NEXP];
#pragma unroll
    for (int e = 0; e < NEXP; e++) acc[e] = 0.0f;
    const float* xr = x + (size_t)t * DDIM;
    for (int d = lane; d < DDIM; d += 32) {
        float xv = __ldg(xr + d);
        const float4* wr = (const float4*)(wg + (size_t)d * NEXP);
        float4 w0 = __ldg(wr), w1 = __ldg(wr + 1);
        acc[0] += xv * w0.x; acc[1] += xv * w0.y; acc[2] += xv * w0.z; acc[3] += xv * w0.w;
        acc[4] += xv * w1.x; acc[5] += xv * w1.y; acc[6] += xv * w1.z; acc[7] += xv * w1.w;
    }
#pragma unroll
    for (int off = 16; off > 0; off >>= 1) {
#pragma unroll
        for (int e = 0; e < NEXP; e++)
            acc[e] += __shfl_xor_sync(0xffffffffu, acc[e], off);
    }
    if (lane == 0) {
        float v1 = -1e30f, v2 = -1e30f; int i1 = 0, i2 = 1;
#pragma unroll
        for (int e = 0; e < NEXP; e++) {
            float v = acc[e];
            if (v > v1)      { v2 = v1; i2 = i1; v1 = v; i1 = e; }
            else if (v > v2) { v2 = v;  i2 = e; }
        }
        float ex = expf(v2 - v1);
        float inv = 1.0f / (1.0f + ex);
        float w1v = inv, w2v = ex * inv;
        int b = __ldg(band + t);
        g_topi[2 * t] = i1;  g_topi[2 * t + 1] = i2;
        g_topw[2 * t] = w1v; g_topw[2 * t + 1] = w2v;
        atomicAdd(&g_bcount[i1 * NBANDS + b], 1);
        atomicAdd(&g_bcount[i2 * NBANDS + b], 1);
        atomicAdd(&g_imp[i1], w1v);
        atomicAdd(&g_imp[i2], w2v);
    }
}

// ---------------- kernel 2: offsets + loss + tile map ----------------
__global__ void offloss_kernel(float* __restrict__ out) {
    if (threadIdx.x != 0 || blockIdx.x != 0) return;
    int off = 0;
    for (int e = 0; e < NEXP; e++) {
        int c = 0;
        for (int b = 0; b < NBANDS; b++) c += g_bcount[e * NBANDS + b];
        g_count[e] = c;
        g_offset[e] = off;
        int o = off;
        for (int b = 0; b < NBANDS; b++) { g_bcursor[e * NBANDS + b] = o; o += g_bcount[e * NBANDS + b]; }
        off += c;
    }
    float mi = 0.0f, ml = 0.0f;
    for (int e = 0; e < NEXP; e++) { mi += g_imp[e]; ml += (float)g_count[e]; }
    mi *= (1.0f / NEXP); ml *= (1.0f / NEXP);
    float vi = 0.0f, vl = 0.0f;
    for (int e = 0; e < NEXP; e++) {
        float di = g_imp[e] - mi;          vi += di * di;
        float dl = (float)g_count[e] - ml; vl += dl * dl;
    }
    vi *= (1.0f / (NEXP - 1)); vl *= (1.0f / (NEXP - 1));
    out[(size_t)NTOK * ODIM] =
        0.01f * (vi / (mi * mi + 1e-10f) + vl / (ml * ml + 1e-10f));
    int nt = 0;
    for (int e = 0; e < NEXP; e++)
        for (int t = 0; t < g_count[e]; t += 128) {
            g_tile_e[nt] = e; g_tile_p0[nt] = g_offset[e] + t; nt++;
        }
    g_ntiles = nt;
}

// ---------------- kernel 3: bucketed scatter ----------------
__global__ void scatter_kernel(const int* __restrict__ band) {
    int t = blockIdx.x * blockDim.x + threadIdx.x;
    if (t >= NTOK) return;
    int b = __ldg(band + t);
#pragma unroll
    for (int k = 0; k < 2; k++) {
        int e = g_topi[2 * t + k];
        float w = g_topw[2 * t + k];
        int p = atomicAdd(&g_bcursor[e * NBANDS + b], 1);
        g_tok[p] = t; g_gw[p] = w; g_eid[p] = e;
    }
}

// ---------------- weight transpose + bf16 split ----------------
// in: [E][K][N] fp32 (N contiguous) -> out hi/lo: [E][N][K] bf16
template <int SEL>
__global__ void wsplit_kernel(const float* __restrict__ in, int K, int N) {
    __shared__ float t[32][33];
    int e = blockIdx.z;
    const float* src = in + (size_t)e * K * N;
    __nv_bfloat16 *dh, *dl;
    if (SEL == 0) { dh = g_w1h; dl = g_w1l; }
    else if (SEL == 1) { dh = g_w2h; dl = g_w2l; }
    else if (SEL == 2) { dh = g_b1h; dl = g_b1l; }
    else { dh = g_b2h; dl = g_b2l; }
    dh += (size_t)e * N * K; dl += (size_t)e * N * K;
    int n0 = blockIdx.x * 32, k0 = blockIdx.y * 32;
    int tx = threadIdx.x, ty = threadIdx.y;
#pragma unroll
    for (int i = 0; i < 4; i++) {
        int k = k0 + ty + i * 8;
        t[ty + i * 8][tx] = __ldg(src + (size_t)k * N + n0 + tx);
    }
    __syncthreads();
#pragma unroll
    for (int i = 0; i < 4; i++) {
        int n = n0 + ty + i * 8, k = k0 + tx;
        float v = t[tx][ty + i * 8];
        __nv_bfloat16 h = __float2bfloat16(v);
        __nv_bfloat16 l = __float2bfloat16(v - __bfloat162float(h));
        dh[(size_t)n * K + k] = h;
        dl[(size_t)n * K + k] = l;
    }
}

// ---------------- x gather + bf16 split pack ----------------
__global__ void xpack_kernel(const float* __restrict__ x) {
    int p = blockIdx.x;
    int t = g_tok[p];
    const float4* src = (const float4*)(x + (size_t)t * DDIM);
    __nv_bfloat16* oh = g_xh + (size_t)p * DDIM;
    __nv_bfloat16* ol = g_xl + (size_t)p * DDIM;
    for (int i = threadIdx.x; i < DDIM / 4; i += 256) {
        float4 v = __ldg(src + i);
        __align__(8) __nv_bfloat16 hb[4], lb[4];
        float vv[4] = {v.x, v.y, v.z, v.w};
#pragma unroll
        for (int k = 0; k < 4; k++) {
            hb[k] = __float2bfloat16(vv[k]);
            lb[k] = __float2bfloat16(vv[k] - __bfloat162float(hb[k]));
        }
        *(uint2*)(oh + i * 4) = *(uint2*)hb;
        *(uint2*)(ol + i * 4) = *(uint2*)lb;
    }
}

// ---------------- LoRA down-projection u = src @ A[e,band], write bf16 ext ----
template <bool FIRST>
__global__ void ured_kernel(const float* __restrict__ src, const float* __restrict__ Amat,
                            const int* __restrict__ band) {
    int lane = threadIdx.x & 31, warp = threadIdx.x >> 5;
    int p = blockIdx.x * 8 + warp;
    if (p >= NPAIR) return;
    int t = g_tok[p];
    int e = g_eid[p];
    int b = __ldg(band + t);
    const int K = FIRST ? DDIM : HDIM;
    const float* A = Amat + (size_t)(e * NBANDS + b) * K * RR;
    float acc[RR];
#pragma unroll
    for (int r = 0; r < RR; r++) acc[r] = 0.0f;
    const float* rowf = FIRST ? (src + (size_t)t * DDIM) : (const float*)0;
    const __nv_bfloat16* rhh = g_hh + (size_t)p * HDIM;
    const __nv_bfloat16* rhl = g_hl + (size_t)p * HDIM;
    for (int d = lane; d < K; d += 32) {
        float v;
        if (FIRST) v = __ldg(rowf + d);
        else       v = __bfloat162float(rhh[d]) + __bfloat162float(rhl[d]);
        const float4* ar = (const float4*)(A + (size_t)d * RR);
        float4 q0 = __ldg(ar + 0), q1 = __ldg(ar + 1), q2 = __ldg(ar + 2), q3 = __ldg(ar + 3);
        acc[0]  += v * q0.x; acc[1]  += v * q0.y; acc[2]  += v * q0.z; acc[3]  += v * q0.w;
        acc[4]  += v * q1.x; acc[5]  += v * q1.y; acc[6]  += v * q1.z; acc[7]  += v * q1.w;
        acc[8]  += v * q2.x; acc[9]  += v * q2.y; acc[10] += v * q2.z; acc[11] += v * q2.w;
        acc[12] += v * q3.x; acc[13] += v * q3.y; acc[14] += v * q3.z; acc[15] += v * q3.w;
    }
#pragma unroll
    for (int off = 16; off > 0; off >>= 1) {
#pragma unroll
        for (int r = 0; r < RR; r++)
            acc[r] += __shfl_xor_sync(0xffffffffu, acc[r], off);
    }
    __nv_bfloat16* uh = (FIRST ? g_xeh : g_u2h) + (size_t)p * REXT;
    __nv_bfloat16* ul = (FIRST ? g_xel : g_u2l) + (size_t)p * REXT;
    __nv_bfloat16 z = __float2bfloat16(0.0f);
    uh[lane] = z; uh[lane + 32] = z;
    ul[lane] = z; ul[lane + 32] = z;
    __syncwarp();
    if (lane < RR) {
        float v = 2.0f * acc[lane];  // SCALING folded
        __nv_bfloat16 h = __float2bfloat16(v);
        __nv_bfloat16 l = __float2bfloat16(v - __bfloat162float(h));
        uh[b * RR + lane] = h;
        ul[b * RR + lane] = l;
    }
}

// ---------------- fused grouped GEMM, mma.sync bf16x3 split ----------------
// FIRST:  g_hh/g_hl[p,:] = split(gelu(x_aug @ W1_aug + b1))   KD=1024, NDIM=4096
// !FIRST: y[tok,:] += gw * (h_aug @ W2_aug + b2)              KD=4096, NDIM=1024
template <bool FIRST, int KD, int NDIM>
__global__ void __launch_bounds__(256, 1)
gemm_mma(const float* __restrict__ bias, float* __restrict__ Yout) {
    int tile = blockIdx.y;
    if (tile >= g_ntiles) return;
    int e    = g_tile_e[tile];
    int p0   = g_tile_p0[tile];
    int pend = g_offset[e] + g_count[e];
    int jb   = blockIdx.x * 128;

    extern __shared__ char sm[];
    uint32_t smb = smem_u32(sm);
    int tid = threadIdx.x, wid = tid >> 5, lane = tid & 31;

    int*   srow = (int*)(sm + 2 * STAGEB);
    float* sgw  = (float*)(sm + 2 * STAGEB + 512);
    if (tid < 128) {
        int p = p0 + tid; if (p >= pend) p = pend - 1;
        srow[tid] = g_tok[p]; sgw[tid] = g_gw[p];
    }

    // ---- cp.async load assignment: 4 tiles (Ah,Al,Bh,Bl) x 64 threads each ----
    int ltile = tid >> 6;            // 0:Ah 1:Al 2:Bh 3:Bl
    int lrow0 = (tid & 63) * 2;      // this thread fills rows lrow0, lrow0+1
    const __nv_bfloat16 *gmain[2], *gext[2];
#pragma unroll
    for (int i = 0; i < 2; i++) {
        int row = lrow0 + i;
        const __nv_bfloat16 *bm, *be;
        if (ltile < 2) {
            int p = p0 + row; if (p >= pend) p = pend - 1;
            if (FIRST) {
                bm = (ltile == 0 ? g_xh : g_xl) + (size_t)p * KD;
                be = (ltile == 0 ? g_xeh : g_xel) + (size_t)p * REXT;
            } else {
                bm = (ltile == 0 ? g_hh : g_hl) + (size_t)p * KD;
                be = (ltile == 0 ? g_u2h : g_u2l) + (size_t)p * REXT;
            }
        } else {
            size_t nr = (size_t)e * NDIM + jb + row;
            if (FIRST) {
                bm = (ltile == 2 ? g_w1h : g_w1l) + nr * KD;
                be = (ltile == 2 ? g_b1h : g_b1l) + nr * REXT;
            } else {
                bm = (ltile == 2 ? g_w2h : g_w2l) + nr * KD;
                be = (ltile == 2 ? g_b2h : g_b2l) + nr * REXT;
            }
        }
        gmain[i] = bm; gext[i] = be;
    }

    const int NCm = KD / 32;
    const int NC  = NCm + 2;       // +2 ext chunks (REXT=64)

    auto ld = [&](int c, int s) {
        uint32_t db = smb + s * STAGEB + ltile * TILEB;
#pragma unroll
        for (int i = 0; i < 2; i++) {
            int row = lrow0 + i;
            const __nv_bfloat16* src =
                (c < NCm) ? (gmain[i] + c * 32) : (gext[i] + (c - NCm) * 32);
            uint32_t d = db + row * TSTRIDE;
            cp16(d, src); cp16(d + 16, src + 8);
            cp16(d + 32, src + 16); cp16(d + 48, src + 24);
        }
        asm volatile("cp.async.commit_group;" ::: "memory");
    };

    // ---- warp tile: 32(m) x 64(n), 4x2 warp grid ----
    int wm = (wid & 3) * 32;
    int wn = (wid >> 2) * 64;
    int a_r  = lane & 15;
    int a_kb = (lane >> 4) * 16;
    int g    = lane >> 3;
    int b_r  = ((g >> 1) * 8) + (lane & 7);
    int b_kb = (g & 1) * 16;

    float acc[2][8][4];
#pragma unroll
    for (int mt = 0; mt < 2; mt++)
#pragma unroll
        for (int nt = 0; nt < 8; nt++)
#pragma unroll
            for (int q = 0; q < 4; q++) acc[mt][nt][q] = 0.0f;

    ld(0, 0);
    for (int c = 0; c < NC; c++) {
        int s = c & 1;
        if (c + 1 < NC) {
            ld(c + 1, s ^ 1);
            asm volatile("cp.async.wait_group 1;" ::: "memory");
        } else {
            asm volatile("cp.async.wait_group 0;" ::: "memory");
        }
        __syncthreads();
        uint32_t Ah = smb + s * STAGEB;
        uint32_t Al = Ah + TILEB, Bh = Ah + 2 * TILEB, Bl = Ah + 3 * TILEB;
#pragma unroll
        for (int ks = 0; ks < 2; ks++) {
            uint32_t kb = ks * 32;
            uint32_t rah[2][4], ral[2][4];
#pragma unroll
            for (int mt = 0; mt < 2; mt++) {
                uint32_t ro = (uint32_t)(wm + mt * 16 + a_r) * TSTRIDE + kb + a_kb;
                ldsm4(rah[mt], Ah + ro);
                ldsm4(ral[mt], Al + ro);
            }
#pragma unroll
            for (int np = 0; np < 4; np++) {
                uint32_t rbh[4], rbl[4];
                uint32_t ro = (uint32_t)(wn + np * 16 + b_r) * TSTRIDE + kb + b_kb;
                ldsm4(rbh, Bh + ro);
                ldsm4(rbl, Bl + ro);
#pragma unroll
                for (int mt = 0; mt < 2; mt++) {
                    mma16816(acc[mt][2 * np],     rah[mt], rbh);
                    mma16816(acc[mt][2 * np],     rah[mt], rbl);
                    mma16816(acc[mt][2 * np],     ral[mt], rbh);
                    mma16816(acc[mt][2 * np + 1], rah[mt], rbh + 2);
                    mma16816(acc[mt][2 * np + 1], rah[mt], rbl + 2);
                    mma16816(acc[mt][2 * np + 1], ral[mt], rbh + 2);
                }
            }
        }
        __syncthreads();
    }

    // ---- epilogue ----
    const float* brow = bias + (size_t)e * NDIM + jb;
    int qr = lane >> 2, qc = (lane & 3) * 2;
#pragma unroll
    for (int mt = 0; mt < 2; mt++) {
#pragma unroll
        for (int nt = 0; nt < 8; nt++) {
            int col = wn + nt * 8 + qc;
            float b0 = __ldg(brow + col), b1 = __ldg(brow + col + 1);
#pragma unroll
            for (int hrow = 0; hrow < 2; hrow++) {
                int m = wm + mt * 16 + qr + hrow * 8;
                int p = p0 + m;
                if (p >= pend) continue;
                float v0 = acc[mt][nt][hrow * 2]     + b0;
                float v1 = acc[mt][nt][hrow * 2 + 1] + b1;
                if (FIRST) {
                    v0 = gelu_exact(v0); v1 = gelu_exact(v1);
                    __nv_bfloat16 h0 = __float2bfloat16(v0);
                    __nv_bfloat16 h1 = __float2bfloat16(v1);
                    __nv_bfloat16 l0 = __float2bfloat16(v0 - __bfloat162float(h0));
                    __nv_bfloat16 l1 = __float2bfloat16(v1 - __bfloat162float(h1));
                    uint32_t hp = (uint32_t)__bfloat16_as_ushort(h0) |
                                  ((uint32_t)__bfloat16_as_ushort(h1) << 16);
                    uint32_t lp = (uint32_t)__bfloat16_as_ushort(l0) |
                                  ((uint32_t)__bfloat16_as_ushort(l1) << 16);
                    size_t off = (size_t)p * NDIM + jb + col;
                    *(uint32_t*)(g_hh + off) = hp;
                    *(uint32_t*)(g_hl + off) = lp;
                } else {
                    int tok = srow[m]; float gw = sgw[m];
                    float* yr = Yout + (size_t)tok * NDIM + jb + col;
                    atomicAdd(yr,     gw * v0);
                    atomicAdd(yr + 1, gw * v1);
                }
            }
        }
    }
}

// ---------------- host launcher ----------------
extern "C" void kernel_launch(void* const* d_in, const int* in_sizes, int n_in,
                              void* d_out, int out_size) {
    const float* x    = (const float*)d_in[0];
    const int*   band = (const int*)  d_in[1];
    const float* wg   = (const float*)d_in[2];
    const float* W1   = (const float*)d_in[3];
    const float* b1   = (const float*)d_in[4];
    const float* W2   = (const float*)d_in[5];
    const float* b2   = (const float*)d_in[6];
    const float* A1   = (const float*)d_in[7];
    const float* B1   = (const float*)d_in[8];
    const float* A2   = (const float*)d_in[9];
    const float* B2   = (const float*)d_in[10];
    float* out = (float*)d_out;

    cudaFuncSetAttribute(gemm_mma<true, DDIM, HDIM>,
                         cudaFuncAttributeMaxDynamicSharedMemorySize, GEMM_SMEM);
    cudaFuncSetAttribute(gemm_mma<false, HDIM, ODIM>,
                         cudaFuncAttributeMaxDynamicSharedMemorySize, GEMM_SMEM);

    cudaMemsetAsync(d_out, 0, (size_t)out_size * sizeof(float));

    init_kernel<<<1, 32>>>();
    gate_kernel<<<NTOK / 8, 256>>>(x, wg, band);
    offloss_kernel<<<1, 32>>>(out);
    scatter_kernel<<<NTOK / 256, 256>>>(band);

    dim3 wb(32, 8);
    wsplit_kernel<0><<<dim3(HDIM / 32, DDIM / 32, NEXP), wb>>>(W1, DDIM, HDIM);
    wsplit_kernel<1><<<dim3(ODIM / 32, HDIM / 32, NEXP), wb>>>(W2, HDIM, ODIM);
    wsplit_kernel<2><<<dim3(HDIM / 32, REXT / 32, NEXP), wb>>>(B1, REXT, HDIM);
    wsplit_kernel<3><<<dim3(ODIM / 32, REXT / 32, NEXP), wb>>>(B2, REXT, ODIM);

    xpack_kernel<<<NPAIR, 256>>>(x);
    ured_kernel<true><<<NPAIR / 8, 256>>>(x, A1, band);

    gemm_mma<true, DDIM, HDIM>
        <<<dim3(HDIM / 128, MAXTILES), 256, GEMM_SMEM>>>(b1, nullptr);

    ured_kernel<false><<<NPAIR / 8, 256>>>(nullptr, A2, band);

    gemm_mma<false, HDIM, ODIM>
        <<<dim3(ODIM / 128, MAXTILES), 256, GEMM_SMEM>>>(b2, out);

    (void)in_sizes; (void)n_in;
}

// round 9
// speedup vs baseline: 1.6818x; 1.2700x over previous
#include <cuda_runtime.h>
#include <cuda_bf16.h>
#include <math.h>
#include <stdint.h>

#define NTOK   16384
#define DDIM   1024
#define HDIM   4096
#define ODIM   1024
#define NEXP   8
#define NBANDS 4
#define RR     16
#define REXT   (NBANDS*RR)      /* 64 */
#define NPAIR  (NTOK*2)         /* 32768 */
#define NBUCK  (NEXP*NBANDS)    /* 32 */
#define MAXTILES 264            /* 32768/128 + 8 */
#define MAXGRP   1088           /* 32768/32 + 32 */

#define TSTRIDE 80              /* bytes per smem tile row (32 bf16 + pad) */
#define SLOTS   768             /* Ah128 + Al128 + Bh256 + Bl256 rows */
#define STAGEB  (SLOTS * TSTRIDE)   /* 61440 */
#define GEMM_SMEM (2 * STAGEB + 1024)

// ---------------- device-global scratch (no allocation allowed) ----------------
__device__ __nv_bfloat16 g_xh [(size_t)NPAIR * DDIM];
__device__ __nv_bfloat16 g_xl [(size_t)NPAIR * DDIM];
__device__ __nv_bfloat16 g_xeh[(size_t)NPAIR * REXT];
__device__ __nv_bfloat16 g_xel[(size_t)NPAIR * REXT];
__device__ __nv_bfloat16 g_hh [(size_t)NPAIR * HDIM];
__device__ __nv_bfloat16 g_hl [(size_t)NPAIR * HDIM];
__device__ __nv_bfloat16 g_u2h[(size_t)NPAIR * REXT];
__device__ __nv_bfloat16 g_u2l[(size_t)NPAIR * REXT];
__device__ __nv_bfloat16 g_w1h[(size_t)NEXP * HDIM * DDIM];  // [E][N=H][K=D]
__device__ __nv_bfloat16 g_w1l[(size_t)NEXP * HDIM * DDIM];
__device__ __nv_bfloat16 g_w2h[(size_t)NEXP * ODIM * HDIM];  // [E][N=O][K=H]
__device__ __nv_bfloat16 g_w2l[(size_t)NEXP * ODIM * HDIM];
__device__ __nv_bfloat16 g_b1h[(size_t)NEXP * HDIM * REXT];  // [E][N=H][K=64]
__device__ __nv_bfloat16 g_b1l[(size_t)NEXP * HDIM * REXT];
__device__ __nv_bfloat16 g_b2h[(size_t)NEXP * ODIM * REXT];
__device__ __nv_bfloat16 g_b2l[(size_t)NEXP * ODIM * REXT];

__device__ int   g_bcount[NBUCK];
__device__ int   g_bcursor[NBUCK];
__device__ int   g_count[NEXP];
__device__ int   g_offset[NEXP];
__device__ float g_imp[NEXP];
__device__ int   g_tok[NPAIR];
__device__ float g_gw[NPAIR];
__device__ int   g_topi[NTOK * 2];
__device__ float g_topw[NTOK * 2];
__device__ int   g_tile_e[MAXTILES];
__device__ int   g_tile_p0[MAXTILES];
__device__ int   g_ntiles;
__device__ int   g_grp_p0[MAXGRP];
__device__ int   g_grp_cnt[MAXGRP];
__device__ int   g_grp_eb[MAXGRP];
__device__ int   g_ngrp;

// ---------------- small helpers ----------------
__device__ __forceinline__ float gelu_exact(float v) {
    return 0.5f * v * (1.0f + erff(v * 0.70710678118654752440f));
}
__device__ __forceinline__ uint32_t smem_u32(const void* p) {
    uint32_t a;
    asm("{ .reg .u64 t; cvta.to.shared.u64 t, %1; cvt.u32.u64 %0, t; }" : "=r"(a) : "l"(p));
    return a;
}
__device__ __forceinline__ void cp16(uint32_t dst, const void* src) {
    asm volatile("cp.async.cg.shared.global [%0], [%1], 16;" :: "r"(dst), "l"(src));
}
__device__ __forceinline__ void ldsm4(uint32_t* r, uint32_t addr) {
    asm volatile("ldmatrix.sync.aligned.m8n8.x4.shared.b16 {%0,%1,%2,%3}, [%4];"
                 : "=r"(r[0]), "=r"(r[1]), "=r"(r[2]), "=r"(r[3]) : "r"(addr));
}
__device__ __forceinline__ void mma16816(float* c, const uint32_t* a, const uint32_t* b) {
    asm volatile(
        "mma.sync.aligned.m16n8k16.row.col.f32.bf16.bf16.f32 "
        "{%0,%1,%2,%3}, {%4,%5,%6,%7}, {%8,%9}, {%0,%1,%2,%3};"
        : "+f"(c[0]), "+f"(c[1]), "+f"(c[2]), "+f"(c[3])
        : "r"(a[0]), "r"(a[1]), "r"(a[2]), "r"(a[3]), "r"(b[0]), "r"(b[1]));
}

// ---------------- kernel 0: init ----------------
__global__ void init_kernel() {
    int t = threadIdx.x;
    if (t < NBUCK) g_bcount[t] = 0;
    if (t < NEXP) g_imp[t] = 0.0f;
}

// ---------------- kernel 1: gating (warp per token) ----------------
__global__ void gate_kernel(const float* __restrict__ x, const float* __restrict__ wg,
                            const int* __restrict__ band) {
    int lane = threadIdx.x & 31, warp = threadIdx.x >> 5;
    int t = blockIdx.x * 8 + warp;
    if (t >= NTOK) return;
    float acc[NEXP];
#pragma unroll
    for (int e = 0; e < NEXP; e++) acc[e] = 0.0f;
    const float* xr = x + (size_t)t * DDIM;
    for (int d = lane; d < DDIM; d += 32) {
        float xv = __ldg(xr + d);
        const float4* wr = (const float4*)(wg + (size_t)d * NEXP);
        float4 w0 = __ldg(wr), w1 = __ldg(wr + 1);
        acc[0] += xv * w0.x; acc[1] += xv * w0.y; acc[2] += xv * w0.z; acc[3] += xv * w0.w;
        acc[4] += xv * w1.x; acc[5] += xv * w1.y; acc[6] += xv * w1.z; acc[7] += xv * w1.w;
    }
#pragma unroll
    for (int off = 16; off > 0; off >>= 1) {
#pragma unroll
        for (int e = 0; e < NEXP; e++)
            acc[e] += __shfl_xor_sync(0xffffffffu, acc[e], off);
    }
    if (lane == 0) {
        float v1 = -1e30f, v2 = -1e30f; int i1 = 0, i2 = 1;
#pragma unroll
        for (int e = 0; e < NEXP; e++) {
            float v = acc[e];
            if (v > v1)      { v2 = v1; i2 = i1; v1 = v; i1 = e; }
            else if (v > v2) { v2 = v;  i2 = e; }
        }
        float ex = expf(v2 - v1);
        float inv = 1.0f / (1.0f + ex);
        float w1v = inv, w2v = ex * inv;
        int b = __ldg(band + t);
        g_topi[2 * t] = i1;  g_topi[2 * t + 1] = i2;
        g_topw[2 * t] = w1v; g_topw[2 * t + 1] = w2v;
        atomicAdd(&g_bcount[i1 * NBANDS + b], 1);
        atomicAdd(&g_bcount[i2 * NBANDS + b], 1);
        atomicAdd(&g_imp[i1], w1v);
        atomicAdd(&g_imp[i2], w2v);
    }
}

// ---------------- kernel 2: offsets + loss + tile map + group map ----------------
__global__ void offloss_kernel(float* __restrict__ out) {
    if (threadIdx.x != 0 || blockIdx.x != 0) return;
    int off = 0, ng = 0;
    for (int e = 0; e < NEXP; e++) {
        int c = 0;
        for (int b = 0; b < NBANDS; b++) c += g_bcount[e * NBANDS + b];
        g_count[e] = c;
        g_offset[e] = off;
        int o = off;
        for (int b = 0; b < NBANDS; b++) {
            int bc = g_bcount[e * NBANDS + b];
            g_bcursor[e * NBANDS + b] = o;
            for (int q = 0; q < bc; q += 32) {
                g_grp_p0[ng] = o + q;
                g_grp_cnt[ng] = (bc - q < 32) ? (bc - q) : 32;
                g_grp_eb[ng] = e * NBANDS + b;
                ng++;
            }
            o += bc;
        }
        off += c;
    }
    g_ngrp = ng;
    float mi = 0.0f, ml = 0.0f;
    for (int e = 0; e < NEXP; e++) { mi += g_imp[e]; ml += (float)g_count[e]; }
    mi *= (1.0f / NEXP); ml *= (1.0f / NEXP);
    float vi = 0.0f, vl = 0.0f;
    for (int e = 0; e < NEXP; e++) {
        float di = g_imp[e] - mi;          vi += di * di;
        float dl = (float)g_count[e] - ml; vl += dl * dl;
    }
    vi *= (1.0f / (NEXP - 1)); vl *= (1.0f / (NEXP - 1));
    out[(size_t)NTOK * ODIM] =
        0.01f * (vi / (mi * mi + 1e-10f) + vl / (ml * ml + 1e-10f));
    int nt = 0;
    for (int e = 0; e < NEXP; e++)
        for (int t = 0; t < g_count[e]; t += 128) {
            g_tile_e[nt] = e; g_tile_p0[nt] = g_offset[e] + t; nt++;
        }
    g_ntiles = nt;
}

// ---------------- kernel 3: bucketed scatter ----------------
__global__ void scatter_kernel(const int* __restrict__ band) {
    int t = blockIdx.x * blockDim.x + threadIdx.x;
    if (t >= NTOK) return;
    int b = __ldg(band + t);
#pragma unroll
    for (int k = 0; k < 2; k++) {
        int e = g_topi[2 * t + k];
        float w = g_topw[2 * t + k];
        int p = atomicAdd(&g_bcursor[e * NBANDS + b], 1);
        g_tok[p] = t; g_gw[p] = w;
    }
}

// ---------------- weight transpose + bf16 split ----------------
template <int SEL>
__global__ void wsplit_kernel(const float* __restrict__ in, int K, int N) {
    __shared__ float t[32][33];
    int e = blockIdx.z;
    const float* src = in + (size_t)e * K * N;
    __nv_bfloat16 *dh, *dl;
    if (SEL == 0) { dh = g_w1h; dl = g_w1l; }
    else if (SEL == 1) { dh = g_w2h; dl = g_w2l; }
    else if (SEL == 2) { dh = g_b1h; dl = g_b1l; }
    else { dh = g_b2h; dl = g_b2l; }
    dh += (size_t)e * N * K; dl += (size_t)e * N * K;
    int n0 = blockIdx.x * 32, k0 = blockIdx.y * 32;
    int tx = threadIdx.x, ty = threadIdx.y;
#pragma unroll
    for (int i = 0; i < 4; i++) {
        int k = k0 + ty + i * 8;
        t[ty + i * 8][tx] = __ldg(src + (size_t)k * N + n0 + tx);
    }
    __syncthreads();
#pragma unroll
    for (int i = 0; i < 4; i++) {
        int n = n0 + ty + i * 8, k = k0 + tx;
        float v = t[tx][ty + i * 8];
        __nv_bfloat16 h = __float2bfloat16(v);
        __nv_bfloat16 l = __float2bfloat16(v - __bfloat162float(h));
        dh[(size_t)n * K + k] = h;
        dl[(size_t)n * K + k] = l;
    }
}

// ---------------- x gather + bf16 split pack ----------------
__global__ void xpack_kernel(const float* __restrict__ x) {
    int p = blockIdx.x;
    int t = g_tok[p];
    const float4* src = (const float4*)(x + (size_t)t * DDIM);
    __nv_bfloat16* oh = g_xh + (size_t)p * DDIM;
    __nv_bfloat16* ol = g_xl + (size_t)p * DDIM;
    for (int i = threadIdx.x; i < DDIM / 4; i += 256) {
        float4 v = __ldg(src + i);
        __align__(8) __nv_bfloat16 hb[4], lb[4];
        float vv[4] = {v.x, v.y, v.z, v.w};
#pragma unroll
        for (int k = 0; k < 4; k++) {
            hb[k] = __float2bfloat16(vv[k]);
            lb[k] = __float2bfloat16(vv[k] - __bfloat162float(hb[k]));
        }
        *(uint2*)(oh + i * 4) = *(uint2*)hb;
        *(uint2*)(ol + i * 4) = *(uint2*)lb;
    }
}

// ---------------- grouped LoRA down-projection: 32 same-bucket pairs / block ----
// FIRST: u1 = x @ A1[e,b]  (K=1024);  !FIRST: u2 = h @ A2[e,b]  (K=4096)
template <bool FIRST>
__global__ void __launch_bounds__(256)
ured_kernel(const float* __restrict__ xsrc, const float* __restrict__ Amat) {
    int gi = blockIdx.x;
    if (gi >= g_ngrp) return;
    int p0 = g_grp_p0[gi], cnt = g_grp_cnt[gi], eb = g_grp_eb[gi];
    int b = eb & (NBANDS - 1);
    const int K = FIRST ? DDIM : HDIM;
    const float* A = Amat + (size_t)eb * K * RR;

    __shared__ float As[128 * 20];   // 128 k-rows x 80B (conflict-free LDS.128)
    uint32_t asb = smem_u32(As);
    int tid = threadIdx.x, wid = tid >> 5, lane = tid & 31;

    const float* xr[4];
    const __nv_bfloat16 *phh[4], *phl[4];
#pragma unroll
    for (int i = 0; i < 4; i++) {
        int p = p0 + wid * 4 + i; if (p >= p0 + cnt) p = p0 + cnt - 1;
        if (FIRST) xr[i] = xsrc + (size_t)g_tok[p] * DDIM;
        else { phh[i] = g_hh + (size_t)p * HDIM; phl[i] = g_hl + (size_t)p * HDIM; }
    }
    float acc[4][16];
#pragma unroll
    for (int i = 0; i < 4; i++)
#pragma unroll
        for (int r = 0; r < 16; r++) acc[i][r] = 0.0f;

    int lr = tid >> 1, lh = tid & 1;
    for (int kc = 0; kc < K; kc += 128) {
        __syncthreads();
        {
            uint32_t d = asb + lr * 80 + lh * 32;
            const float* s = A + (size_t)(kc + lr) * RR + lh * 8;
            cp16(d, s); cp16(d + 16, s + 4);
        }
        asm volatile("cp.async.commit_group;" ::: "memory");
        asm volatile("cp.async.wait_group 0;" ::: "memory");
        __syncthreads();
#pragma unroll
        for (int i = 0; i < 4; i++) {
#pragma unroll
            for (int j = 0; j < 4; j++) {
                int dd = lane + j * 32;
                float v;
                if (FIRST) v = __ldg(xr[i] + kc + dd);
                else v = __bfloat162float(phh[i][kc + dd]) + __bfloat162float(phl[i][kc + dd]);
                const float4* ar = (const float4*)(As + dd * 20);
                float4 q0 = ar[0], q1 = ar[1], q2 = ar[2], q3 = ar[3];
                acc[i][0]  += v * q0.x; acc[i][1]  += v * q0.y; acc[i][2]  += v * q0.z; acc[i][3]  += v * q0.w;
                acc[i][4]  += v * q1.x; acc[i][5]  += v * q1.y; acc[i][6]  += v * q1.z; acc[i][7]  += v * q1.w;
                acc[i][8]  += v * q2.x; acc[i][9]  += v * q2.y; acc[i][10] += v * q2.z; acc[i][11] += v * q2.w;
                acc[i][12] += v * q3.x; acc[i][13] += v * q3.y; acc[i][14] += v * q3.z; acc[i][15] += v * q3.w;
            }
        }
    }
#pragma unroll
    for (int i = 0; i < 4; i++) {
#pragma unroll
        for (int off = 16; off > 0; off >>= 1)
#pragma unroll
            for (int r = 0; r < 16; r++)
                acc[i][r] += __shfl_xor_sync(0xffffffffu, acc[i][r], off);
        int p = p0 + wid * 4 + i;
        if (p < p0 + cnt) {
            __nv_bfloat16* uh = (FIRST ? g_xeh : g_u2h) + (size_t)p * REXT;
            __nv_bfloat16* ul = (FIRST ? g_xel : g_u2l) + (size_t)p * REXT;
            __nv_bfloat16 z = __float2bfloat16(0.0f);
            uh[lane] = z; uh[lane + 32] = z;
            ul[lane] = z; ul[lane + 32] = z;
            __syncwarp();
            if (lane < RR) {
                float v = 2.0f * acc[i][lane];   // SCALING folded
                __nv_bfloat16 h = __float2bfloat16(v);
                __nv_bfloat16 l = __float2bfloat16(v - __bfloat162float(h));
                uh[b * RR + lane] = h;
                ul[b * RR + lane] = l;
            }
        }
    }
}

// ---------------- fused grouped GEMM, mma.sync bf16x3, 128x256 tile ----------------
// FIRST:  g_hh/g_hl[p,:] = split(gelu(x_aug @ W1_aug + b1))   KD=1024, NDIM=4096
// !FIRST: y[tok,:] += gw * (h_aug @ W2_aug + b2)              KD=4096, NDIM=1024
template <bool FIRST, int KD, int NDIM>
__global__ void __launch_bounds__(256, 1)
gemm_mma(const float* __restrict__ bias, float* __restrict__ Yout) {
    int tile = blockIdx.y;
    if (tile >= g_ntiles) return;
    int e    = g_tile_e[tile];
    int p0   = g_tile_p0[tile];
    int pend = g_offset[e] + g_count[e];
    int jb   = blockIdx.x * 256;

    extern __shared__ char sm[];
    uint32_t smb = smem_u32(sm);
    int tid = threadIdx.x, wid = tid >> 5, lane = tid & 31;

    int*   srow = (int*)(sm + 2 * STAGEB);
    float* sgw  = (float*)(sm + 2 * STAGEB + 512);
    if (tid < 128) {
        int p = p0 + tid; if (p >= pend) p = pend - 1;
        srow[tid] = g_tok[p]; sgw[tid] = g_gw[p];
    }

    // ---- load assignment: 3 row-slots per thread ----
    // slot0 = tid        : Ah row tid (tid<128) / Al row tid-128
    // slot1 = 256 + tid  : Bh row tid
    // slot2 = 512 + tid  : Bl row tid
    const __nv_bfloat16 *m0, *e0, *m1, *e1, *m2, *e2;
    {
        int ar = tid & 127;
        int p = p0 + ar; if (p >= pend) p = pend - 1;
        bool hi = tid < 128;
        if (FIRST) {
            m0 = (hi ? g_xh : g_xl) + (size_t)p * KD;
            e0 = (hi ? g_xeh : g_xel) + (size_t)p * REXT;
        } else {
            m0 = (hi ? g_hh : g_hl) + (size_t)p * KD;
            e0 = (hi ? g_u2h : g_u2l) + (size_t)p * REXT;
        }
        size_t nr = (size_t)e * NDIM + jb + tid;
        if (FIRST) {
            m1 = g_w1h + nr * KD; e1 = g_b1h + nr * REXT;
            m2 = g_w1l + nr * KD; e2 = g_b1l + nr * REXT;
        } else {
            m1 = g_w2h + nr * KD; e1 = g_b2h + nr * REXT;
            m2 = g_w2l + nr * KD; e2 = g_b2l + nr * REXT;
        }
    }
    const int NCm = KD / 32;
    const int NC  = NCm + 2;

    uint32_t d0b = smb + (uint32_t)tid * TSTRIDE;
    uint32_t d1b = smb + (uint32_t)(256 + tid) * TSTRIDE;
    uint32_t d2b = smb + (uint32_t)(512 + tid) * TSTRIDE;

    auto ld = [&](int c, int s) {
        uint32_t so = s * STAGEB;
        const __nv_bfloat16* s0 = (c < NCm) ? m0 + c * 32 : e0 + (c - NCm) * 32;
        const __nv_bfloat16* s1 = (c < NCm) ? m1 + c * 32 : e1 + (c - NCm) * 32;
        const __nv_bfloat16* s2 = (c < NCm) ? m2 + c * 32 : e2 + (c - NCm) * 32;
        uint32_t d0 = d0b + so, d1 = d1b + so, d2 = d2b + so;
        cp16(d0, s0); cp16(d0 + 16, s0 + 8); cp16(d0 + 32, s0 + 16); cp16(d0 + 48, s0 + 24);
        cp16(d1, s1); cp16(d1 + 16, s1 + 8); cp16(d1 + 32, s1 + 16); cp16(d1 + 48, s1 + 24);
        cp16(d2, s2); cp16(d2 + 16, s2 + 8); cp16(d2 + 32, s2 + 16); cp16(d2 + 48, s2 + 24);
        asm volatile("cp.async.commit_group;" ::: "memory");
    };

    // ---- warp tile: 64(m) x 64(n); 2m x 4n warp grid ----
    int wm = (wid & 1) * 64;
    int wn = (wid >> 1) * 64;
    int a_r  = lane & 15;
    int a_kb = (lane >> 4) * 16;
    int g2   = lane >> 3;
    int b_r  = ((g2 >> 1) * 8) + (lane & 7);
    int b_kb = (g2 & 1) * 16;

    float acc[4][8][4];
#pragma unroll
    for (int mt = 0; mt < 4; mt++)
#pragma unroll
        for (int nt = 0; nt < 8; nt++)
#pragma unroll
            for (int q = 0; q < 4; q++) acc[mt][nt][q] = 0.0f;

    ld(0, 0);
    for (int c = 0; c < NC; c++) {
        int s = c & 1;
        if (c + 1 < NC) {
            ld(c + 1, s ^ 1);
            asm volatile("cp.async.wait_group 1;" ::: "memory");
        } else {
            asm volatile("cp.async.wait_group 0;" ::: "memory");
        }
        __syncthreads();
        uint32_t Ah = smb + s * STAGEB;
        uint32_t Al = Ah + 128 * TSTRIDE;
        uint32_t Bh = Ah + 256 * TSTRIDE;
        uint32_t Bl = Ah + 512 * TSTRIDE;
#pragma unroll
        for (int ks = 0; ks < 2; ks++) {
            uint32_t kb = ks * 32;
            uint32_t rah[4][4], ral[4][4];
#pragma unroll
            for (int mt = 0; mt < 4; mt++) {
                uint32_t ro = (uint32_t)(wm + mt * 16 + a_r) * TSTRIDE + kb + a_kb;
                ldsm4(rah[mt], Ah + ro);
                ldsm4(ral[mt], Al + ro);
            }
#pragma unroll
            for (int np = 0; np < 4; np++) {
                uint32_t rbh[4], rbl[4];
                uint32_t ro = (uint32_t)(wn + np * 16 + b_r) * TSTRIDE + kb + b_kb;
                ldsm4(rbh, Bh + ro);
                ldsm4(rbl, Bl + ro);
#pragma unroll
                for (int mt = 0; mt < 4; mt++) {
                    mma16816(acc[mt][2 * np],     rah[mt], rbh);
                    mma16816(acc[mt][2 * np],     rah[mt], rbl);
                    mma16816(acc[mt][2 * np],     ral[mt], rbh);
                    mma16816(acc[mt][2 * np + 1], rah[mt], rbh + 2);
                    mma16816(acc[mt][2 * np + 1], rah[mt], rbl + 2);
                    mma16816(acc[mt][2 * np + 1], ral[mt], rbh + 2);
                }
            }
        }
        __syncthreads();
    }

    // ---- epilogue ----
    const float* brow = bias + (size_t)e * NDIM + jb;
    int qr = lane >> 2, qc = (lane & 3) * 2;
#pragma unroll
    for (int mt = 0; mt < 4; mt++) {
#pragma unroll
        for (int nt = 0; nt < 8; nt++) {
            int col = wn + nt * 8 + qc;
            float b0 = __ldg(brow + col), b1 = __ldg(brow + col + 1);
#pragma unroll
            for (int hrow = 0; hrow < 2; hrow++) {
                int m = wm + mt * 16 + qr + hrow * 8;
                int p = p0 + m;
                if (p >= pend) continue;
                float v0 = acc[mt][nt][hrow * 2]     + b0;
                float v1 = acc[mt][nt][hrow * 2 + 1] + b1;
                if (FIRST) {
                    v0 = gelu_exact(v0); v1 = gelu_exact(v1);
                    __nv_bfloat16 h0 = __float2bfloat16(v0);
                    __nv_bfloat16 h1 = __float2bfloat16(v1);
                    __nv_bfloat16 l0 = __float2bfloat16(v0 - __bfloat162float(h0));
                    __nv_bfloat16 l1 = __float2bfloat16(v1 - __bfloat162float(h1));
                    uint32_t hp = (uint32_t)__bfloat16_as_ushort(h0) |
                                  ((uint32_t)__bfloat16_as_ushort(h1) << 16);
                    uint32_t lp = (uint32_t)__bfloat16_as_ushort(l0) |
                                  ((uint32_t)__bfloat16_as_ushort(l1) << 16);
                    size_t off = (size_t)p * NDIM + jb + col;
                    *(uint32_t*)(g_hh + off) = hp;
                    *(uint32_t*)(g_hl + off) = lp;
                } else {
                    int tok = srow[m]; float gw = sgw[m];
                    float* yr = Yout + (size_t)tok * NDIM + jb + col;
                    atomicAdd(yr,     gw * v0);
                    atomicAdd(yr + 1, gw * v1);
                }
            }
        }
    }
}

// ---------------- host launcher ----------------
extern "C" void kernel_launch(void* const* d_in, const int* in_sizes, int n_in,
                              void* d_out, int out_size) {
    const float* x    = (const float*)d_in[0];
    const int*   band = (const int*)  d_in[1];
    const float* wg   = (const float*)d_in[2];
    const float* W1   = (const float*)d_in[3];
    const float* b1   = (const float*)d_in[4];
    const float* W2   = (const float*)d_in[5];
    const float* b2   = (const float*)d_in[6];
    const float* A1   = (const float*)d_in[7];
    const float* B1   = (const float*)d_in[8];
    const float* A2   = (const float*)d_in[9];
    const float* B2   = (const float*)d_in[10];
    float* out = (float*)d_out;

    cudaFuncSetAttribute(gemm_mma<true, DDIM, HDIM>,
                         cudaFuncAttributeMaxDynamicSharedMemorySize, GEMM_SMEM);
    cudaFuncSetAttribute(gemm_mma<false, HDIM, ODIM>,
                         cudaFuncAttributeMaxDynamicSharedMemorySize, GEMM_SMEM);

    cudaMemsetAsync(d_out, 0, (size_t)out_size * sizeof(float));

    init_kernel<<<1, 32>>>();
    gate_kernel<<<NTOK / 8, 256>>>(x, wg, band);
    offloss_kernel<<<1, 32>>>(out);
    scatter_kernel<<<NTOK / 256, 256>>>(band);

    dim3 wb(32, 8);
    wsplit_kernel<0><<<dim3(HDIM / 32, DDIM / 32, NEXP), wb>>>(W1, DDIM, HDIM);
    wsplit_kernel<1><<<dim3(ODIM / 32, HDIM / 32, NEXP), wb>>>(W2, HDIM, ODIM);
    wsplit_kernel<2><<<dim3(HDIM / 32, REXT / 32, NEXP), wb>>>(B1, REXT, HDIM);
    wsplit_kernel<3><<<dim3(ODIM / 32, REXT / 32, NEXP), wb>>>(B2, REXT, ODIM);

    xpack_kernel<<<NPAIR, 256>>>(x);
    ured_kernel<true><<<MAXGRP, 256>>>(x, A1);

    gemm_mma<true, DDIM, HDIM>
        <<<dim3(HDIM / 256, MAXTILES), 256, GEMM_SMEM>>>(b1, nullptr);

    ured_kernel<false><<<MAXGRP, 256>>>(nullptr, A2);

    gemm_mma<false, HDIM, ODIM>
        <<<dim3(ODIM / 256, MAXTILES), 256, GEMM_SMEM>>>(b2, out);

    (void)in_sizes; (void)n_in;
}